// round 2
// baseline (speedup 1.0000x reference)
#include <cuda_runtime.h>

#define HH 4096
#define WW 1024
#define SS 16
#define NSEG 17

// Scratch (allocation-free rule: __device__ globals)
__device__ float g_predsT[WW * HH];   // 16 MB: preds transposed to [W][H]
__device__ float g_wstd[WW];
__device__ float g_msk[WW];

// ---------------------------------------------------------------------------
// Kernel 1: transpose preds [H][W] -> g_predsT [W][H]
// ---------------------------------------------------------------------------
__global__ void k_transpose(const float* __restrict__ in) {
    __shared__ float tile[32][33];
    int x = blockIdx.x * 32 + threadIdx.x;   // w
    int y = blockIdx.y * 32 + threadIdx.y;   // h
#pragma unroll
    for (int j = 0; j < 32; j += 8)
        tile[threadIdx.y + j][threadIdx.x] = in[(size_t)(y + j) * WW + x];
    __syncthreads();
    int x2 = blockIdx.y * 32 + threadIdx.x;  // h
    int y2 = blockIdx.x * 32 + threadIdx.y;  // w
#pragma unroll
    for (int j = 0; j < 32; j += 8)
        g_predsT[(size_t)(y2 + j) * HH + x2] = tile[threadIdx.x][threadIdx.y + j];
}

// ---------------------------------------------------------------------------
// Kernel 2: one block per column (256 threads, 16 rows/thread).
// Two-level scan (2 barriers) + hard segment moments from registers + soft
// sigmoid-window corrections around each boundary.
// ---------------------------------------------------------------------------
__global__ void __launch_bounds__(256) k_column(const float* __restrict__ snakes) {
    __shared__ float r[HH];           // normalized cumsum
    __shared__ float snk[SS];
    __shared__ float x0[NSEG];        // per-segment shift (cum at segment midpoint)
    __shared__ float segB[NSEG], segA[NSEG], segC[NSEG];
    __shared__ float P0[SS], PAu[SS], PCu[SS], PAl[SS], PCl[SS];
    __shared__ float warpsum[8];
    __shared__ float wvar_s;

    const int w    = blockIdx.x;
    const int tid  = threadIdx.x;
    const int lane = tid & 31;
    const int wid  = tid >> 5;

    if (tid < SS) snk[tid] = snakes[tid * WW + w];
    if (tid < NSEG) { segB[tid] = 0.f; segA[tid] = 0.f; segC[tid] = 0.f; }
    if (tid == 0) wvar_s = 0.f;
    __syncthreads();

    const float* col = g_predsT + (size_t)w * HH;
    const int base = tid * 16;

    // ---- load 16 contiguous rows, sequential inclusive scan in registers ----
    float x[16];
    {
        const float4* c4 = (const float4*)(col + base);
        float4 a0 = c4[0], a1 = c4[1], a2 = c4[2], a3 = c4[3];
        float run = 0.f;
        run += a0.x; x[0]  = run;  run += a0.y; x[1]  = run;
        run += a0.z; x[2]  = run;  run += a0.w; x[3]  = run;
        run += a1.x; x[4]  = run;  run += a1.y; x[5]  = run;
        run += a1.z; x[6]  = run;  run += a1.w; x[7]  = run;
        run += a2.x; x[8]  = run;  run += a2.y; x[9]  = run;
        run += a2.z; x[10] = run;  run += a2.w; x[11] = run;
        run += a3.x; x[12] = run;  run += a3.y; x[13] = run;
        run += a3.z; x[14] = run;  run += a3.w; x[15] = run;
    }
    const float tot = x[15];

    // ---- warp inclusive scan over per-thread totals ----
    float sc = tot;
#pragma unroll
    for (int d = 1; d < 32; d <<= 1) {
        float n = __shfl_up_sync(0xffffffffu, sc, d);
        if (lane >= d) sc += n;
    }
    if (lane == 31) warpsum[wid] = sc;
    __syncthreads();

    float carry = 0.f, mag = 0.f;
#pragma unroll
    for (int k = 0; k < 8; k++) {
        float ws = warpsum[k];
        if (k < wid) carry += ws;
        mag += ws;
    }
    const float offset = carry + (sc - tot);   // exclusive prefix for this thread
    const float inv = 1.0f / mag;

#pragma unroll
    for (int k = 0; k < 16; k++) {
        x[k] = (x[k] + offset) * inv;
        r[base + k] = x[k];
    }
    __syncthreads();

    // ---- per-segment shift points: cum at segment midpoint ----
    if (tid < NSEG) {
        float sL = (tid == 0)  ? 0.f       : snk[tid - 1];
        float sR = (tid == SS) ? (float)HH : snk[tid];
        int m = (int)(0.5f * (sL + sR));
        m = min(max(m, 0), HH - 1);
        x0[tid] = r[m];
    }
    __syncthreads();

    // ---- hard pass: row h -> hard segment j = #{i : s_i <= h}; accumulate
    //      (1, x-x0_j, (x-x0_j)^2) in registers, flush on segment change ----
    {
        int j = 0;
#pragma unroll
        for (int i = 0; i < SS; i++) j += (snk[i] <= (float)base) ? 1 : 0;
        float sNext = (j < SS) ? snk[j] : 3.0e38f;
        float xc = x0[j];
        float b = 0.f, a = 0.f, cc = 0.f;
#pragma unroll
        for (int k = 0; k < 16; k++) {
            float hf = (float)(base + k);
            if (hf >= sNext) {
                atomicAdd(&segB[j], b); atomicAdd(&segA[j], a); atomicAdd(&segC[j], cc);
                b = a = cc = 0.f;
                do { j++; } while (j < SS && snk[j] <= hf);
                sNext = (j < SS) ? snk[j] : 3.0e38f;
                xc = x0[j];
            }
            float xv = x[k] - xc;
            b += 1.f; a += xv; cc += xv * xv;
        }
        atomicAdd(&segB[j], b); atomicAdd(&segA[j], a); atomicAdd(&segC[j], cc);
    }
    __syncthreads();

    // ---- soft corrections: delta = sigmoid(s-h) - step(s-h), only within
    //      +/-20 rows of a boundary (|delta| < e^-20 outside). One warp per
    //      2 boundaries; sums taken with BOTH adjacent segments' shifts. ----
    for (int b = wid; b < SS; b += 8) {
        float s = snk[b];
        int lo = max(0, (int)ceilf(s - 20.f));
        int hi = min(HH, (int)floorf(s + 20.f) + 1);
        float xu = x0[b], xl = x0[b + 1];
        float p0 = 0.f, pau = 0.f, pcu = 0.f, pal = 0.f, pcl = 0.f;
        for (int h = lo + lane; h < hi; h += 32) {
            float t = s - (float)h;
            float u = __expf(-fabsf(t));
            float sg = u / (1.f + u);
            float dlt = (t > 0.f) ? -sg : sg;   // sigma - step, stable both sides
            float xv = r[h];
            float du = xv - xu, dl = xv - xl;
            p0  += dlt;
            pau += dlt * du;  pcu += dlt * du * du;
            pal += dlt * dl;  pcl += dlt * dl * dl;
        }
#pragma unroll
        for (int d = 16; d; d >>= 1) {
            p0  += __shfl_xor_sync(0xffffffffu, p0, d);
            pau += __shfl_xor_sync(0xffffffffu, pau, d);
            pcu += __shfl_xor_sync(0xffffffffu, pcu, d);
            pal += __shfl_xor_sync(0xffffffffu, pal, d);
            pcl += __shfl_xor_sync(0xffffffffu, pcl, d);
        }
        if (lane == 0) { P0[b] = p0; PAu[b] = pau; PCu[b] = pcu; PAl[b] = pal; PCl[b] = pcl; }
    }
    __syncthreads();

    // ---- combine: segment i gets +window(i) (shift x0[i]) - window(i-1)
    //      (lower-side sums also taken with shift x0[i]) ----
    if (tid < NSEG) {
        int i = tid;
        float B = segB[i] + ((i < SS) ? P0[i]  : 0.f) - ((i > 0) ? P0[i - 1]  : 0.f);
        float A = segA[i] + ((i < SS) ? PAu[i] : 0.f) - ((i > 0) ? PAl[i - 1] : 0.f);
        float C = segC[i] + ((i < SS) ? PCu[i] : 0.f) - ((i > 0) ? PCl[i - 1] : 0.f);
        float wv = (B > 1e-20f) ? (C - A * A / B) : 0.f;
        atomicAdd(&wvar_s, wv);
    }
    __syncthreads();

    if (tid == 0) {
        float wstd = wvar_s / (float)(NSEG * HH);
        bool m = (mag > 1.0f);
        g_wstd[w] = m ? wstd : 0.f;
        g_msk[w]  = m ? 1.f : 0.f;
    }
}

// ---------------------------------------------------------------------------
// Kernel 3: reduce 1024 columns -> scalar loss
// ---------------------------------------------------------------------------
__global__ void k_reduce(float* __restrict__ out) {
    int tid = threadIdx.x;
    float s = 0.f, c = 0.f;
    for (int i = tid; i < WW; i += 256) { s += g_wstd[i]; c += g_msk[i]; }
#pragma unroll
    for (int d = 16; d; d >>= 1) {
        s += __shfl_xor_sync(0xffffffffu, s, d);
        c += __shfl_xor_sync(0xffffffffu, c, d);
    }
    __shared__ float ws[8], wc[8];
    if ((tid & 31) == 0) { ws[tid >> 5] = s; wc[tid >> 5] = c; }
    __syncthreads();
    if (tid == 0) {
        float S_ = 0.f, C_ = 0.f;
#pragma unroll
        for (int k = 0; k < 8; k++) { S_ += ws[k]; C_ += wc[k]; }
        out[0] = S_ / C_;
    }
}

// ---------------------------------------------------------------------------
extern "C" void kernel_launch(void* const* d_in, const int* in_sizes, int n_in,
                              void* d_out, int out_size) {
    const float* snakes = (const float*)d_in[0];   // [S=16, W=1024]
    const float* preds  = (const float*)d_in[1];   // [H=4096, W=1024]
    (void)in_sizes; (void)n_in; (void)out_size;

    dim3 tb(32, 8);
    k_transpose<<<dim3(WW / 32, HH / 32), tb>>>(preds);
    k_column<<<WW, 256>>>(snakes);
    k_reduce<<<1, 256>>>((float*)d_out);
}